// round 2
// baseline (speedup 1.0000x reference)
#include <cuda_runtime.h>

#define BSZ   2
#define C_IN  64
#define NPTS  1024
#define NA    60
#define NO    60
#define KS    3
#define ANN   8
#define CO    128
#define CK    192            // C_IN * KS
#define NCOLS (NPTS * NO)    // 61440
#define BSROW 132            // padded smem row for B tile (32 x 128 chunk)

typedef unsigned long long u64;

// ---------------- device scratch (static allocation: allowed) ----------------
__device__ float g_x[(size_t)BSZ * CK * NCOLS];   // gathered x, 94.4 MB
__device__ float g_wt[CK * CO];                   // W transposed to [k][m]

// ---------------- packed fp32x2 helpers ----------------
__device__ __forceinline__ u64 pk2(float lo, float hi) {
    u64 r; asm("mov.b64 %0, {%1, %2};" : "=l"(r) : "f"(lo), "f"(hi)); return r;
}
__device__ __forceinline__ void upk2(u64 v, float& lo, float& hi) {
    asm("mov.b64 {%0, %1}, %2;" : "=f"(lo), "=f"(hi) : "l"(v));
}
__device__ __forceinline__ void fma2(u64& d, u64 a, u64 b) {
    asm("fma.rn.f32x2 %0, %1, %2, %3;" : "=l"(d) : "l"(a), "l"(b), "l"(d));
}

// ---------------- kernel 0: transpose W into k-major ----------------
__global__ void k_wt(const float* __restrict__ W) {
    int i = blockIdx.x * 256 + threadIdx.x;
    if (i < CK * CO) {
        int k = i / CO, m = i - k * CO;
        g_wt[i] = W[m * CK + k];
    }
}

// ---------------- kernel 1: gather + intra-weight combine ----------------
// One CTA per (p, b). Warp lanes span c (conflict-free via 61-col pad);
// (o,k) uniform per warp-group -> idx/weight reads are broadcasts.
__global__ __launch_bounds__(256) void k_gather(const float* __restrict__ feats,
                                                const float* __restrict__ wv,
                                                const int*   __restrict__ widx) {
    extern __shared__ float smem1[];
    float* Xs = smem1;                        // 64 * 61
    float* Gr = Xs + C_IN * (NA + 1);         // 192 * 60
    float* sw = Gr + CK * NO;                 // 1440
    int*   si = (int*)(sw + NO * KS * ANN);   // 1440

    int tid = threadIdx.x;
    int p = blockIdx.x, b = blockIdx.y;

    for (int i = tid; i < NO * KS * ANN; i += 256) { sw[i] = wv[i]; si[i] = widx[i]; }

    const float* fb = feats + ((size_t)b * C_IN * NPTS + p) * NA;
    for (int i = tid; i < C_IN * NA; i += 256) {
        int c = i / NA, a = i - c * NA;
        Xs[c * (NA + 1) + a] = fb[(size_t)c * NPTS * NA + a];
    }
    __syncthreads();

    int c = tid & 63, g = tid >> 6;
    for (int ok = g; ok < NO * KS; ok += 4) {
        int o = ok / KS, k = ok - o * KS;
        const float* wp = sw + ok * ANN;
        const int*   ip = si + ok * ANN;
        float acc = 0.f;
        #pragma unroll
        for (int j = 0; j < ANN; ++j)
            acc += wp[j] * Xs[c * (NA + 1) + ip[j]];
        Gr[(c * KS + k) * NO + o] = acc;
    }
    __syncthreads();

    // coalesced write: x[b][ck][p*60 + o]
    float* xb = g_x + (size_t)b * CK * NCOLS + (size_t)p * NO;
    for (int i = tid; i < CK * NO; i += 256) {
        int ck = i / NO, o = i - ck * NO;
        xb[(size_t)ck * NCOLS + o] = Gr[i];
    }
}

// ---------------- kernel 2: out = W @ x + bias (f32x2-packed SGEMM) ----------------
// CTA tile: 128(m) x 128(n), K = 192 in six 32-row chunks with register prefetch.
__global__ __launch_bounds__(256) void k_gemm(const float* __restrict__ bias,
                                              float* __restrict__ out) {
    extern __shared__ float smem2[];
    float* Wt_s = smem2;           // 192 * 128
    float* Bsm  = smem2 + CK * CO; // 32 * 132

    int tid = threadIdx.x;
    int n0 = blockIdx.x * 128;
    int b  = blockIdx.y;

    for (int i = tid * 4; i < CK * CO; i += 1024)
        *(float4*)(Wt_s + i) = *(const float4*)(g_wt + i);

    const float* xb = g_x + (size_t)b * CK * NCOLS + n0;

    float4 pre[4];
    #pragma unroll
    for (int q = 0; q < 4; ++q) {
        int idx = q * 256 + tid, kr = idx >> 5, nc = (idx & 31) * 4;
        pre[q] = *(const float4*)(xb + (size_t)kr * NCOLS + nc);
    }

    int ty = tid >> 4, tx = tid & 15;
    int m0 = ty * 8, nl = tx * 8;

    u64 acc[8][4];
    #pragma unroll
    for (int m = 0; m < 8; ++m)
        #pragma unroll
        for (int n = 0; n < 4; ++n) acc[m][n] = pk2(0.f, 0.f);

    for (int ch = 0; ch < 6; ++ch) {
        __syncthreads();
        #pragma unroll
        for (int q = 0; q < 4; ++q) {
            int idx = q * 256 + tid, kr = idx >> 5, nc = (idx & 31) * 4;
            *(float4*)(Bsm + kr * BSROW + nc) = pre[q];
        }
        __syncthreads();
        if (ch < 5) {
            #pragma unroll
            for (int q = 0; q < 4; ++q) {
                int idx = q * 256 + tid, kr = idx >> 5, nc = (idx & 31) * 4;
                pre[q] = *(const float4*)(xb + (size_t)((ch + 1) * 32 + kr) * NCOLS + nc);
            }
        }
        const float* wk = Wt_s + (ch * 32) * CO + m0;
        #pragma unroll 4
        for (int kk = 0; kk < 32; ++kk) {
            float4 a0 = *(const float4*)(wk + kk * CO);
            float4 a1 = *(const float4*)(wk + kk * CO + 4);
            const float* bp = Bsm + kk * BSROW + nl;
            u64 b0 = *(const u64*)(bp);
            u64 b1 = *(const u64*)(bp + 2);
            u64 b2 = *(const u64*)(bp + 4);
            u64 b3 = *(const u64*)(bp + 6);
            float am[8] = {a0.x, a0.y, a0.z, a0.w, a1.x, a1.y, a1.z, a1.w};
            #pragma unroll
            for (int m = 0; m < 8; ++m) {
                u64 ad = pk2(am[m], am[m]);
                fma2(acc[m][0], ad, b0);
                fma2(acc[m][1], ad, b1);
                fma2(acc[m][2], ad, b2);
                fma2(acc[m][3], ad, b3);
            }
        }
    }

    #pragma unroll
    for (int m = 0; m < 8; ++m) {
        float bz = bias[m0 + m];
        float v[8];
        upk2(acc[m][0], v[0], v[1]);
        upk2(acc[m][1], v[2], v[3]);
        upk2(acc[m][2], v[4], v[5]);
        upk2(acc[m][3], v[6], v[7]);
        float4 o0 = {v[0] + bz, v[1] + bz, v[2] + bz, v[3] + bz};
        float4 o1 = {v[4] + bz, v[5] + bz, v[6] + bz, v[7] + bz};
        float* op = out + (size_t)(b * CO + m0 + m) * NCOLS + n0 + nl;
        *(float4*)op = o0;
        *(float4*)(op + 4) = o1;
    }
}

// ---------------- host launcher ----------------
extern "C" void kernel_launch(void* const* d_in, const int* in_sizes, int n_in,
                              void* d_out, int out_size) {
    const float* feats     = (const float*)d_in[0];  // (2,64,1024,60) f32
    const float* intra_w   = (const float*)d_in[1];  // (60,3,8) f32
    const float* W         = (const float*)d_in[2];  // (128,192) f32
    const float* bias      = (const float*)d_in[3];  // (1,128,1) f32
    const int*   intra_idx = (const int*)d_in[4];    // (60,3,8) i32
    float* out = (float*)d_out;

    const int SMEM1 = (C_IN * (NA + 1) + CK * NO + 2 * NO * KS * ANN) * 4;  // 73216
    const int SMEM2 = (CK * CO + 32 * BSROW) * 4;                            // 115200

    cudaFuncSetAttribute(k_gather, cudaFuncAttributeMaxDynamicSharedMemorySize, SMEM1);
    cudaFuncSetAttribute(k_gemm,   cudaFuncAttributeMaxDynamicSharedMemorySize, SMEM2);

    k_wt<<<(CK * CO + 255) / 256, 256>>>(W);
    k_gather<<<dim3(NPTS, BSZ), 256, SMEM1>>>(feats, intra_w, intra_idx);
    k_gemm<<<dim3(NCOLS / 128, BSZ), 256, SMEM2>>>(bias, out);
}

// round 4
// speedup vs baseline: 1.2094x; 1.2094x over previous
#include <cuda_runtime.h>
#include <cstdint>

#define BSZ   2
#define C_IN  64
#define NPTS  1024
#define NA    60
#define NO    60
#define KS    3
#define ANN   8
#define CO    128
#define CK    192            // GEMM K
#define NCOLS (NPTS * NO)    // 61440  (GEMM N per b)
#define NT    128            // GEMM N tile
#define NTILES_B (NCOLS / NT)       // 480
#define TILES    (BSZ * NTILES_B)   // 960
#define GRID_GEMM 148

#define WPAD 196             // W smem row stride (floats): bank=(4r+c)%32 conflict-free
#define BPAD 36              // B smem row stride (floats): bank=(4n+k)%32 conflict-free
#define BCH  (NT * BPAD)     // floats per B chunk buffer (128*36)

// ---------------- device scratch ----------------
// x^T layout: [b][n][k], k contiguous (768B rows)
__device__ float g_x[(size_t)BSZ * NCOLS * CK];   // 94.4 MB

// ---------------- helpers ----------------
__device__ __forceinline__ float tf32r(float x) {
    float r; asm("cvt.rna.tf32.f32 %0, %1;" : "=f"(r) : "f"(x)); return r;
}
__device__ __forceinline__ void mma_tf32(float* d, const uint32_t* a, uint32_t b0, uint32_t b1) {
    asm volatile("mma.sync.aligned.m16n8k8.row.col.f32.tf32.tf32.f32 "
        "{%0,%1,%2,%3}, {%4,%5,%6,%7}, {%8,%9}, {%0,%1,%2,%3};"
        : "+f"(d[0]), "+f"(d[1]), "+f"(d[2]), "+f"(d[3])
        : "r"(a[0]), "r"(a[1]), "r"(a[2]), "r"(a[3]), "r"(b0), "r"(b1));
}

// ---------------- kernel 1: gather + intra-weight combine ----------------
// One CTA per (p, b). Output: g_x[b][n][k], n = p*60+o, k = c*3+ks.
__global__ __launch_bounds__(256) void k_gather(const float* __restrict__ feats,
                                                const float* __restrict__ wv,
                                                const int*   __restrict__ widx) {
    extern __shared__ float smem1[];
    float* Xs = smem1;                        // 64 * 61
    float* Gr = Xs + C_IN * (NA + 1);         // 60 * 192   [o][ck]
    float* sw = Gr + NO * CK;                 // 1440
    int*   si = (int*)(sw + NO * KS * ANN);   // 1440

    int tid = threadIdx.x;
    int p = blockIdx.x, b = blockIdx.y;

    for (int i = tid; i < NO * KS * ANN; i += 256) { sw[i] = wv[i]; si[i] = widx[i]; }

    const float* fb = feats + ((size_t)b * C_IN * NPTS + p) * NA;
    for (int i = tid; i < C_IN * NA; i += 256) {
        int c = i / NA, a = i - c * NA;
        Xs[c * (NA + 1) + a] = fb[(size_t)c * NPTS * NA + a];
    }
    __syncthreads();

    int c = tid & 63, g = tid >> 6;
    for (int ok = g; ok < NO * KS; ok += 4) {
        int o = ok / KS, k = ok - o * KS;
        const float* wp = sw + ok * ANN;
        const int*   ip = si + ok * ANN;
        float acc = 0.f;
        #pragma unroll
        for (int j = 0; j < ANN; ++j)
            acc += wp[j] * Xs[c * (NA + 1) + ip[j]];
        Gr[o * CK + c * KS + k] = acc;
    }
    __syncthreads();

    float* xb = g_x + ((size_t)b * NCOLS + (size_t)p * NO) * CK;
    const float4* Gr4 = (const float4*)Gr;
    float4* xb4 = (float4*)xb;
    for (int i = tid; i < NO * CK / 4; i += 256) xb4[i] = Gr4[i];
}

// ---------------- kernel 2: mma.sync TF32 GEMM (3xTF32 split) ----------------
// Persistent CTAs, tile 128m x 128n, K=192 in six 32-chunks (double-buffered,
// hi/lo split fused into the B smem store). W fp32 resident in smem.
__global__ __launch_bounds__(256, 1) void k_gemm_mma(const float* __restrict__ W,
                                                     const float* __restrict__ bias,
                                                     float* __restrict__ out) {
    extern __shared__ float sm[];
    float* Wsm = sm;                     // 128 * 196
    float* Bh  = sm + CO * WPAD;         // 2 * BCH
    float* Bl  = Bh + 2 * BCH;           // 2 * BCH

    int tid = threadIdx.x;
    int wid = tid >> 5, lane = tid & 31;
    int wm = (wid & 3) * 32;             // warp m-offset (4 warps over m)
    int wn = (wid >> 2) * 64;            // warp n-offset (2 warps over n)
    int lr = lane >> 2, lc = lane & 3;

    // resident W load (row-major, padded)
    for (int i = tid * 4; i < CO * CK; i += 1024) {
        int m = i / CK, k = i - m * CK;
        *(float4*)(Wsm + m * WPAD + k) = *(const float4*)(W + i);
    }
    // bias for this thread's output rows (fixed across tiles)
    float bz[2][2];
    #pragma unroll
    for (int mt = 0; mt < 2; ++mt) {
        bz[mt][0] = bias[wm + mt * 16 + lr];
        bz[mt][1] = bias[wm + mt * 16 + lr + 8];
    }
    __syncthreads();

    for (int t = blockIdx.x; t < TILES; t += GRID_GEMM) {
        int b = t / NTILES_B;
        int n0 = (t - b * NTILES_B) * NT;
        const float* xb = g_x + ((size_t)b * NCOLS + n0) * CK;

        // prefetch chunk 0 (each thread: 4 float4 = 16 floats of the 16KB chunk)
        float4 pre[4];
        #pragma unroll
        for (int q = 0; q < 4; ++q) {
            int idx = q * 256 + tid, n = idx >> 3, kq = idx & 7;
            pre[q] = *(const float4*)(xb + (size_t)n * CK + kq * 4);
        }

        float d[2][8][4];
        #pragma unroll
        for (int mt = 0; mt < 2; ++mt)
            #pragma unroll
            for (int nt = 0; nt < 8; ++nt)
                #pragma unroll
                for (int r = 0; r < 4; ++r) d[mt][nt][r] = 0.f;

        #pragma unroll 1
        for (int ch = 0; ch < 6; ++ch) {
            int buf = ch & 1;
            float* bhb = Bh + buf * BCH;
            float* blb = Bl + buf * BCH;
            // store prefetched chunk with fused hi/lo tf32 split
            #pragma unroll
            for (int q = 0; q < 4; ++q) {
                int idx = q * 256 + tid, n = idx >> 3, kq = idx & 7;
                float4 v = pre[q], h, l;
                h.x = tf32r(v.x); l.x = tf32r(v.x - h.x);
                h.y = tf32r(v.y); l.y = tf32r(v.y - h.y);
                h.z = tf32r(v.z); l.z = tf32r(v.z - h.z);
                h.w = tf32r(v.w); l.w = tf32r(v.w - h.w);
                *(float4*)(bhb + n * BPAD + kq * 4) = h;
                *(float4*)(blb + n * BPAD + kq * 4) = l;
            }
            __syncthreads();
            // prefetch next chunk under the mma
            if (ch < 5) {
                #pragma unroll
                for (int q = 0; q < 4; ++q) {
                    int idx = q * 256 + tid, n = idx >> 3, kq = idx & 7;
                    pre[q] = *(const float4*)(xb + (size_t)n * CK + (ch + 1) * 32 + kq * 4);
                }
            }
            // mma over 4 k-steps of 8
            #pragma unroll
            for (int ks = 0; ks < 4; ++ks) {
                uint32_t ah[2][4], al[2][4];
                #pragma unroll
                for (int mt = 0; mt < 2; ++mt)
                    #pragma unroll
                    for (int r = 0; r < 4; ++r) {
                        int row = wm + mt * 16 + lr + (r & 1) * 8;
                        int col = ch * 32 + ks * 8 + lc + (r >> 1) * 4;
                        float v = Wsm[row * WPAD + col];
                        float h = tf32r(v);
                        ah[mt][r] = __float_as_uint(h);
                        al[mt][r] = __float_as_uint(tf32r(v - h));
                    }
                #pragma unroll
                for (int nt = 0; nt < 8; ++nt) {
                    int base = (wn + nt * 8 + lr) * BPAD + ks * 8 + lc;
                    uint32_t bh0 = __float_as_uint(bhb[base]);
                    uint32_t bh1 = __float_as_uint(bhb[base + 4]);
                    uint32_t bl0 = __float_as_uint(blb[base]);
                    uint32_t bl1 = __float_as_uint(blb[base + 4]);
                    #pragma unroll
                    for (int mt = 0; mt < 2; ++mt) {
                        mma_tf32(d[mt][nt], ah[mt], bh0, bh1);
                        mma_tf32(d[mt][nt], ah[mt], bl0, bl1);
                        mma_tf32(d[mt][nt], al[mt], bh0, bh1);
                    }
                }
            }
            __syncthreads();
        }

        // epilogue: direct STG.64 (+bias)
        #pragma unroll
        for (int mt = 0; mt < 2; ++mt) {
            int m0 = wm + mt * 16 + lr;
            size_t ro0 = ((size_t)b * CO + m0) * NCOLS + n0 + wn + 2 * lc;
            size_t ro1 = ro0 + (size_t)8 * NCOLS;
            #pragma unroll
            for (int nt = 0; nt < 8; ++nt) {
                float2 v0 = { d[mt][nt][0] + bz[mt][0], d[mt][nt][1] + bz[mt][0] };
                float2 v1 = { d[mt][nt][2] + bz[mt][1], d[mt][nt][3] + bz[mt][1] };
                *(float2*)(out + ro0 + nt * 8) = v0;
                *(float2*)(out + ro1 + nt * 8) = v1;
            }
        }
    }
}

// ---------------- host launcher ----------------
extern "C" void kernel_launch(void* const* d_in, const int* in_sizes, int n_in,
                              void* d_out, int out_size) {
    const float* feats     = (const float*)d_in[0];  // (2,64,1024,60) f32
    const float* intra_w   = (const float*)d_in[1];  // (60,3,8) f32
    const float* W         = (const float*)d_in[2];  // (128,192) f32
    const float* bias      = (const float*)d_in[3];  // (1,128,1) f32
    const int*   intra_idx = (const int*)d_in[4];    // (60,3,8) i32
    float* out = (float*)d_out;

    const int SMEM1 = (C_IN * (NA + 1) + NO * CK + 2 * NO * KS * ANN) * 4;    // 73216
    const int SMEM2 = (CO * WPAD + 4 * BCH) * 4;                              // 174080

    static int configured = 0;
    if (!configured) {
        cudaFuncSetAttribute(k_gather,   cudaFuncAttributeMaxDynamicSharedMemorySize, SMEM1);
        cudaFuncSetAttribute(k_gemm_mma, cudaFuncAttributeMaxDynamicSharedMemorySize, SMEM2);
        configured = 1;
    }

    k_gather<<<dim3(NPTS, BSZ), 256, SMEM1>>>(feats, intra_w, intra_idx);
    k_gemm_mma<<<GRID_GEMM, 256, SMEM2>>>(W, bias, out);
}